// round 15
// baseline (speedup 1.0000x reference)
#include <cuda_runtime.h>
#include <cstdint>
#include <math.h>

#define FULL 0xffffffffu

static constexpr int B_   = 256;
static constexpr int D_   = 128;
static constexpr int DIN_ = 2048;
static constexpr int M_   = 4096;
static constexpr float TAU_INV = 1.0f / 0.07f;

// ---------------- device scratch ----------------
__device__ float g_raw[B_ * D_];        // un-normalized emb (+bias), 128 KB
__device__ float g_pssq[B_ * 64];       // per-d-slice (2-wide) partial sum-of-squares
__device__ float g_acc[2];              // [0]=sum data softplus, [1]=sum noise softplus

// ---------------- A: GEMM with W slice in SMEM, small blocks -----------------
// grid 512 = 64 d-slices (2 cols) x 8 b-groups (32 rows). 128 threads = 4 warps,
// ~4-6 blocks/SM (one full wave). Warp w owns 8 b-rows x 2 d-cols.
// W slice (2 x 2048 fp32 = 16 KB) staged once in static smem.
__global__ void __launch_bounds__(128, 6)
kGemm(const float* __restrict__ outputs,
      const float* __restrict__ W,
      const float* __restrict__ bias) {
    __shared__ float4 sW4[2 * 512];       // 16 KB
    int ds  = blockIdx.x & 63;            // d-slice 0..63 (2 d each)
    int bgr = blockIdx.x >> 6;            // b-group 0..7 (32 b each)
    int tid = threadIdx.x, w = tid >> 5, lane = tid & 31;

    // stage W rows [ds*2, ds*2+2) -- coalesced, 8 float4 per thread
    {
        const float4* src = (const float4*)W + (size_t)(ds * 2) * (DIN_ / 4);
#pragma unroll
        for (int i = 0; i < 8; i++)
            sW4[i * 128 + tid] = src[i * 128 + tid];
    }
    __syncthreads();

    // mainloop: 8 b-rows per warp, 2 d each, K=2048 via 16 iters of 128
    int b0 = bgr * 32 + w * 8;
    const float4* o4 = (const float4*)outputs;

    float acc[8][2];
#pragma unroll
    for (int bi = 0; bi < 8; bi++)
#pragma unroll
        for (int dd = 0; dd < 2; dd++) acc[bi][dd] = 0.0f;

#pragma unroll 2
    for (int it = 0; it < 16; it++) {
        float4 ov[8];
#pragma unroll
        for (int bi = 0; bi < 8; bi++)
            ov[bi] = o4[(size_t)(b0 + bi) * (DIN_ / 4) + it * 32 + lane];
#pragma unroll
        for (int dd = 0; dd < 2; dd++) {
            float4 wv = sW4[dd * 512 + it * 32 + lane];
#pragma unroll
            for (int bi = 0; bi < 8; bi++) {
                float a = acc[bi][dd];
                a = fmaf(wv.x, ov[bi].x, a);
                a = fmaf(wv.y, ov[bi].y, a);
                a = fmaf(wv.z, ov[bi].z, a);
                a = fmaf(wv.w, ov[bi].w, a);
                acc[bi][dd] = a;
            }
        }
    }

    // reduce all 16 accs across lanes; lane bi*2+dd keeps its value
    float mine = 0.0f;
#pragma unroll
    for (int bi = 0; bi < 8; bi++)
#pragma unroll
        for (int dd = 0; dd < 2; dd++) {
            float r = acc[bi][dd];
#pragma unroll
            for (int o = 16; o; o >>= 1) r += __shfl_xor_sync(FULL, r, o);
            if (lane == bi * 2 + dd) mine = r;
        }

    if (lane < 16) {
        int dd_l = lane & 1, bi_l = lane >> 1;
        int d = ds * 2 + dd_l;
        int b = b0 + bi_l;
        mine += bias[d];
        g_raw[b * D_ + d] = mine;

        // partial sum-of-squares over this slice's 2 d (2-lane groups)
        float sq = mine * mine;
        sq += __shfl_xor_sync(0x0000ffffu, sq, 1);
        if (dd_l == 0) g_pssq[b * 64 + ds] = sq;
    }

    if (blockIdx.x == 0 && tid == 0) { g_acc[0] = 0.0f; g_acc[1] = 0.0f; }
}

// ---------------- B: main gather + logsumexp + losses + entries --------------
// One block per batch row. 16 warps; warp w handles negs [w*256, w*256+256).
// (R9 body; prologue reduces 64 pssq partials.)
__global__ void __launch_bounds__(512, 2) kMain(
    const float* __restrict__ mbank,
    const int*   __restrict__ indices,
    const int*   __restrict__ ridx,
    float*       __restrict__ out) {
    int b = blockIdx.x;
    int tid = threadIdx.x, w = tid >> 5, lane = tid & 31;

    __shared__ float sneg[M_];
    __shared__ float sr[33];

    // normalize e on load: ssq = sum of 64 slice partials
    float ssq = g_pssq[b * 64 + lane] + g_pssq[b * 64 + 32 + lane];
#pragma unroll
    for (int o = 16; o; o >>= 1) ssq += __shfl_xor_sync(FULL, ssq, o);
    float inv = 1.0f / fmaxf(sqrtf(ssq), 1e-12f);

    float4 e = ((const float4*)g_raw)[b * 32 + lane];
    e.x *= inv; e.y *= inv; e.z *= inv; e.w *= inv;

    const float4* mb4 = (const float4*)mbank;
    const int* ri = ridx + (size_t)b * M_;

    // ---- gather + dot: 256 negs per warp ----
    int m0 = w * 256;
    for (int mb_ = m0; mb_ < m0 + 256; mb_ += 32) {
        int myIdx = ri[mb_ + lane];
#pragma unroll 8
        for (int j = 0; j < 32; j++) {
            int idx = __shfl_sync(FULL, myIdx, j);
            float4 v = mb4[(size_t)idx * 32 + lane];
            float d = v.x * e.x + v.y * e.y;
            d = fmaf(v.z, e.z, d);
            d = fmaf(v.w, e.w, d);
#pragma unroll
            for (int o = 16; o; o >>= 1) d += __shfl_xor_sync(FULL, d, o);
            if (lane == j) sneg[mb_ + j] = d * TAU_INV;
        }
    }
    __syncthreads();

    // ---- each thread owns 8 negs (stride 512, conflict-free) ----
    float vl[8];
    float mx = -3.0e38f;
#pragma unroll
    for (int i = 0; i < 8; i++) {
        vl[i] = sneg[tid + i * 512];
        mx = fmaxf(mx, vl[i]);
    }
#pragma unroll
    for (int o = 16; o; o >>= 1) mx = fmaxf(mx, __shfl_xor_sync(FULL, mx, o));
    if (lane == 0) sr[w] = mx;
    __syncthreads();
    if (w == 0) {
        float t2 = sr[lane & 15];
#pragma unroll
        for (int o = 8; o; o >>= 1) t2 = fmaxf(t2, __shfl_xor_sync(FULL, t2, o));
        if (lane == 0) sr[32] = t2;
    }
    __syncthreads();
    float Mx = sr[32];

    float se = 0.f;
#pragma unroll
    for (int i = 0; i < 8; i++) se += __expf(vl[i] - Mx);
#pragma unroll
    for (int o = 16; o; o >>= 1) se += __shfl_xor_sync(FULL, se, o);
    __syncthreads();
    if (lane == 0) sr[w] = se;
    __syncthreads();
    if (w == 0) {
        float t2 = (lane < 16) ? sr[lane] : 0.f;
#pragma unroll
        for (int o = 8; o; o >>= 1) t2 += __shfl_xor_sync(FULL, t2, o);
        if (lane == 0) sr[32] = Mx + __logf(t2);
    }
    __syncthreads();
    float logC = sr[32];

    // noise loss: sum softplus(neg - logC)
    float ns = 0.f;
#pragma unroll
    for (int i = 0; i < 8; i++) {
        float x = vl[i] - logC;
        ns += (x > 15.f) ? x : log1pf(__expf(x));
    }
#pragma unroll
    for (int o = 16; o; o >>= 1) ns += __shfl_xor_sync(FULL, ns, o);
    __syncthreads();
    if (lane == 0) sr[w] = ns;
    __syncthreads();
    if (w == 0) {
        float t2 = (lane < 16) ? sr[lane] : 0.f;
#pragma unroll
        for (int o = 8; o; o >>= 1) t2 += __shfl_xor_sync(FULL, t2, o);
        if (lane == 0) atomicAdd(&g_acc[1], t2);
    }

    // ---- warp 0: positive term + entries ----
    if (w == 0) {
        int pidx = indices[b];
        float4 p = mb4[(size_t)pidx * 32 + lane];
        float d = p.x * e.x + p.y * e.y;
        d = fmaf(p.z, e.z, d);
        d = fmaf(p.w, e.w, d);
#pragma unroll
        for (int o = 16; o; o >>= 1) d += __shfl_xor_sync(FULL, d, o);
        float pos = d * TAU_INV;

        float4 ent;
        ent.x = 0.5f * (p.x + e.x);
        ent.y = 0.5f * (p.y + e.y);
        ent.z = 0.5f * (p.z + e.z);
        ent.w = 0.5f * (p.w + e.w);
        float nsq = ent.x * ent.x + ent.y * ent.y + ent.z * ent.z + ent.w * ent.w;
#pragma unroll
        for (int o = 16; o; o >>= 1) nsq += __shfl_xor_sync(FULL, nsq, o);
        float inv2 = 1.0f / fmaxf(sqrtf(nsq), 1e-12f);
        ent.x *= inv2; ent.y *= inv2; ent.z *= inv2; ent.w *= inv2;

        int base = 1 + b * D_ + lane * 4;
        out[base + 0] = ent.x;
        out[base + 1] = ent.y;
        out[base + 2] = ent.z;
        out[base + 3] = ent.w;

        if (lane == 0) {
            float x = logC - pos;
            float dl = (x > 15.f) ? x : log1pf(__expf(x));
            atomicAdd(&g_acc[0], dl);
        }
    }
}

// ---------------- C: finalize scalars ----------------------------------------
__global__ void kFinal(float* __restrict__ out) {
    float dl = g_acc[0] * (1.0f / (float)B_);
    float nl = g_acc[1] * (1.0f / (float)B_);
    out[0] = dl + nl;
    out[1 + B_ * D_]     = dl;
    out[1 + B_ * D_ + 1] = nl;
}

// ---------------- launcher ----------------------------------------------------
extern "C" void kernel_launch(void* const* d_in, const int* in_sizes, int n_in,
                              void* d_out, int out_size) {
    const float* outputs = (const float*)d_in[0];
    const float* W       = (const float*)d_in[1];
    const float* bias    = (const float*)d_in[2];
    const float* mbank   = (const float*)d_in[3];
    const int*   indices = (const int*)d_in[4];
    const int*   ridx    = (const int*)d_in[5];
    float* out = (float*)d_out;

    kGemm<<<512, 128>>>(outputs, W, bias);
    kMain<<<256, 512>>>(mbank, indices, ridx, out);
    kFinal<<<1, 1>>>(out);
}

// round 16
// speedup vs baseline: 1.0396x; 1.0396x over previous
#include <cuda_runtime.h>
#include <cstdint>
#include <math.h>

#define FULL 0xffffffffu

static constexpr int B_   = 256;
static constexpr int D_   = 128;
static constexpr int DIN_ = 2048;
static constexpr int M_   = 4096;
static constexpr float TAU_INV = 1.0f / 0.07f;

// ---------------- device scratch ----------------
__device__ float g_dl[B_];   // per-row data-loss softplus
__device__ float g_nl[B_];   // per-row noise-loss softplus sum

// ---------------- B: fused GEMM + gather + losses + entries ------------------
// One block per batch row (256 blocks x 512 threads).
// Phase 1: emb[b] = l2norm(outputs[b] @ W^T + bias) computed in-block.
// Phase 2: gather 4096 negs, logsumexp, losses, entries (R9 body).
__global__ void __launch_bounds__(512, 2) kMain(
    const float* __restrict__ outputs,
    const float* __restrict__ W,
    const float* __restrict__ bias,
    const float* __restrict__ mbank,
    const int*   __restrict__ indices,
    const int*   __restrict__ ridx,
    float*       __restrict__ out) {
    int b = blockIdx.x;
    int tid = threadIdx.x, w = tid >> 5, lane = tid & 31;

    __shared__ float sneg[M_];
    __shared__ float so[DIN_];     // outputs row (8 KB)
    __shared__ float semb[D_];     // emb_raw + bias
    __shared__ float sr[33];

    // ---- phase 1a: stage outputs[b] ----
    {
        const float4* src = (const float4*)(outputs + (size_t)b * DIN_);
        float4* dst = (float4*)so;
        if (tid < 512) dst[tid] = src[tid];   // 512 float4 = 2048 floats
    }
    __syncthreads();

    // ---- phase 1b: GEMM. warp w computes d in [8w, 8w+8) ----
    {
        int d0 = w * 8;
        const float4* w4 = (const float4*)W;
        const float4* so4 = (const float4*)so;
        float acc[8];
#pragma unroll
        for (int dd = 0; dd < 8; dd++) acc[dd] = 0.0f;

#pragma unroll 4
        for (int it = 0; it < 16; it++) {
            float4 ov = so4[it * 32 + lane];
#pragma unroll
            for (int dd = 0; dd < 8; dd++) {
                float4 wv = w4[(size_t)(d0 + dd) * (DIN_ / 4) + it * 32 + lane];
                float a = acc[dd];
                a = fmaf(wv.x, ov.x, a);
                a = fmaf(wv.y, ov.y, a);
                a = fmaf(wv.z, ov.z, a);
                a = fmaf(wv.w, ov.w, a);
                acc[dd] = a;
            }
        }
        // butterfly each of the 8 sums; lane dd stores d0+dd
        float mine = 0.0f;
#pragma unroll
        for (int dd = 0; dd < 8; dd++) {
            float r = acc[dd];
#pragma unroll
            for (int o = 16; o; o >>= 1) r += __shfl_xor_sync(FULL, r, o);
            if (lane == dd) mine = r;
        }
        if (lane < 8) semb[d0 + lane] = mine + bias[d0 + lane];
    }
    __syncthreads();

    // ---- phase 1c: normalize (each warp redundantly from smem) ----
    float4 e = ((const float4*)semb)[lane];
    float ssq = e.x * e.x + e.y * e.y + e.z * e.z + e.w * e.w;
#pragma unroll
    for (int o = 16; o; o >>= 1) ssq += __shfl_xor_sync(FULL, ssq, o);
    float inv = 1.0f / fmaxf(sqrtf(ssq), 1e-12f);
    e.x *= inv; e.y *= inv; e.z *= inv; e.w *= inv;

    const float4* mb4 = (const float4*)mbank;
    const int* ri = ridx + (size_t)b * M_;

    // ---- phase 2: gather + dot: 256 negs per warp ----
    int m0 = w * 256;
    for (int mb_ = m0; mb_ < m0 + 256; mb_ += 32) {
        int myIdx = ri[mb_ + lane];
#pragma unroll 8
        for (int j = 0; j < 32; j++) {
            int idx = __shfl_sync(FULL, myIdx, j);
            float4 v = mb4[(size_t)idx * 32 + lane];
            float d = v.x * e.x + v.y * e.y;
            d = fmaf(v.z, e.z, d);
            d = fmaf(v.w, e.w, d);
#pragma unroll
            for (int o = 16; o; o >>= 1) d += __shfl_xor_sync(FULL, d, o);
            if (lane == j) sneg[mb_ + j] = d * TAU_INV;
        }
    }
    __syncthreads();

    // ---- each thread owns 8 negs (stride 512, conflict-free) ----
    float vl[8];
    float mx = -3.0e38f;
#pragma unroll
    for (int i = 0; i < 8; i++) {
        vl[i] = sneg[tid + i * 512];
        mx = fmaxf(mx, vl[i]);
    }
#pragma unroll
    for (int o = 16; o; o >>= 1) mx = fmaxf(mx, __shfl_xor_sync(FULL, mx, o));
    if (lane == 0) sr[w] = mx;
    __syncthreads();
    if (w == 0) {
        float t2 = sr[lane & 15];
#pragma unroll
        for (int o = 8; o; o >>= 1) t2 = fmaxf(t2, __shfl_xor_sync(FULL, t2, o));
        if (lane == 0) sr[32] = t2;
    }
    __syncthreads();
    float Mx = sr[32];

    float se = 0.f;
#pragma unroll
    for (int i = 0; i < 8; i++) se += __expf(vl[i] - Mx);
#pragma unroll
    for (int o = 16; o; o >>= 1) se += __shfl_xor_sync(FULL, se, o);
    __syncthreads();
    if (lane == 0) sr[w] = se;
    __syncthreads();
    if (w == 0) {
        float t2 = (lane < 16) ? sr[lane] : 0.f;
#pragma unroll
        for (int o = 8; o; o >>= 1) t2 += __shfl_xor_sync(FULL, t2, o);
        if (lane == 0) sr[32] = Mx + __logf(t2);
    }
    __syncthreads();
    float logC = sr[32];

    // noise loss: sum softplus(neg - logC)
    float ns = 0.f;
#pragma unroll
    for (int i = 0; i < 8; i++) {
        float x = vl[i] - logC;
        ns += (x > 15.f) ? x : log1pf(__expf(x));
    }
#pragma unroll
    for (int o = 16; o; o >>= 1) ns += __shfl_xor_sync(FULL, ns, o);
    __syncthreads();
    if (lane == 0) sr[w] = ns;
    __syncthreads();
    if (w == 0) {
        float t2 = (lane < 16) ? sr[lane] : 0.f;
#pragma unroll
        for (int o = 8; o; o >>= 1) t2 += __shfl_xor_sync(FULL, t2, o);
        if (lane == 0) g_nl[b] = t2;
    }

    // ---- warp 0: positive term + entries ----
    if (w == 0) {
        int pidx = indices[b];
        float4 p = mb4[(size_t)pidx * 32 + lane];
        float d = p.x * e.x + p.y * e.y;
        d = fmaf(p.z, e.z, d);
        d = fmaf(p.w, e.w, d);
#pragma unroll
        for (int o = 16; o; o >>= 1) d += __shfl_xor_sync(FULL, d, o);
        float pos = d * TAU_INV;

        float4 ent;
        ent.x = 0.5f * (p.x + e.x);
        ent.y = 0.5f * (p.y + e.y);
        ent.z = 0.5f * (p.z + e.z);
        ent.w = 0.5f * (p.w + e.w);
        float nsq = ent.x * ent.x + ent.y * ent.y + ent.z * ent.z + ent.w * ent.w;
#pragma unroll
        for (int o = 16; o; o >>= 1) nsq += __shfl_xor_sync(FULL, nsq, o);
        float inv2 = 1.0f / fmaxf(sqrtf(nsq), 1e-12f);
        ent.x *= inv2; ent.y *= inv2; ent.z *= inv2; ent.w *= inv2;

        int base = 1 + b * D_ + lane * 4;
        out[base + 0] = ent.x;
        out[base + 1] = ent.y;
        out[base + 2] = ent.z;
        out[base + 3] = ent.w;

        if (lane == 0) {
            float x = logC - pos;
            g_dl[b] = (x > 15.f) ? x : log1pf(__expf(x));
        }
    }
}

// ---------------- C: finalize scalars (reduce 256 per-row losses) ------------
__global__ void __launch_bounds__(256) kFinal(float* __restrict__ out) {
    __shared__ float s[16];
    int tid = threadIdx.x, w = tid >> 5, lane = tid & 31;
    float dl = g_dl[tid];
    float nl = g_nl[tid];
#pragma unroll
    for (int o = 16; o; o >>= 1) {
        dl += __shfl_xor_sync(FULL, dl, o);
        nl += __shfl_xor_sync(FULL, nl, o);
    }
    if (lane == 0) { s[w] = dl; s[w + 8] = nl; }
    __syncthreads();
    if (tid == 0) {
        float dsum = 0.f, nsum = 0.f;
#pragma unroll
        for (int i = 0; i < 8; i++) { dsum += s[i]; nsum += s[i + 8]; }
        dsum *= (1.0f / (float)B_);
        nsum *= (1.0f / (float)B_);
        out[0] = dsum + nsum;
        out[1 + B_ * D_]     = dsum;
        out[1 + B_ * D_ + 1] = nsum;
    }
}

// ---------------- launcher ----------------------------------------------------
extern "C" void kernel_launch(void* const* d_in, const int* in_sizes, int n_in,
                              void* d_out, int out_size) {
    const float* outputs = (const float*)d_in[0];
    const float* W       = (const float*)d_in[1];
    const float* bias    = (const float*)d_in[2];
    const float* mbank   = (const float*)d_in[3];
    const int*   indices = (const int*)d_in[4];
    const int*   ridx    = (const int*)d_in[5];
    float* out = (float*)d_out;

    kMain<<<256, 512>>>(outputs, W, bias, mbank, indices, ridx, out);
    kFinal<<<1, 256>>>(out);
}

// round 17
// speedup vs baseline: 1.0717x; 1.0308x over previous
#include <cuda_runtime.h>
#include <cstdint>
#include <math.h>

#define FULL 0xffffffffu

static constexpr int B_   = 256;
static constexpr int D_   = 128;
static constexpr int DIN_ = 2048;
static constexpr int M_   = 4096;
static constexpr float TAU_INV = 1.0f / 0.07f;

// dynamic smem layout (floats): so8[8*2048] | sneg[4096] | semb[128] | sr[33]
static constexpr int SMEM_FLOATS = 8 * DIN_ + M_ + D_ + 33;
static constexpr int SMEM_BYTES  = SMEM_FLOATS * 4;   // 82564 B

// ---------------- device scratch ----------------
__device__ float g_dl[B_];   // per-row data-loss softplus
__device__ float g_nl[B_];   // per-row noise-loss softplus sum

// ---------------- cluster helpers ----------------
__device__ __forceinline__ void cluster_sync_() {
    asm volatile("barrier.cluster.arrive.aligned;" ::: "memory");
    asm volatile("barrier.cluster.wait.aligned;" ::: "memory");
}
__device__ __forceinline__ unsigned mapa_shared_(unsigned smem_addr, unsigned rank) {
    unsigned r;
    asm("mapa.shared::cluster.u32 %0, %1, %2;" : "=r"(r) : "r"(smem_addr), "r"(rank));
    return r;
}
__device__ __forceinline__ void st_shared_cluster_f32_(unsigned addr, float v) {
    asm volatile("st.shared::cluster.f32 [%0], %1;" :: "r"(addr), "f"(v) : "memory");
}

// ---------------- fused kernel: GEMM prologue (cluster-8) + gather + losses --
// One block per batch row; the 8 CTAs of a cluster cooperate on the GEMM:
// CTA r computes d in [16r, 16r+16) for all 8 rows of its octet, scattering
// results to owner CTAs via DSMEM. W traffic: 32 MB total (vs 256 MB fused-naive).
__global__ void __cluster_dims__(8, 1, 1) __launch_bounds__(512, 2)
kMain(const float* __restrict__ outputs,
      const float* __restrict__ W,
      const float* __restrict__ bias,
      const float* __restrict__ mbank,
      const int*   __restrict__ indices,
      const int*   __restrict__ ridx,
      float*       __restrict__ out) {
    extern __shared__ float smem[];
    float* so8  = smem;                     // 8 rows of outputs (64 KB)
    float* sneg = smem + 8 * DIN_;          // 4096 neg logits (16 KB)
    float* semb = smem + 8 * DIN_ + M_;     // this row's emb_raw+bias (512 B)
    float* sr   = semb + D_;                // reduction scratch

    int b = blockIdx.x;
    int r = b & 7;                          // cluster rank
    int tid = threadIdx.x, w = tid >> 5, lane = tid & 31;

    // ---- stage the octet's 8 outputs rows ----
    {
        const float4* src = (const float4*)(outputs + (size_t)(b & ~7) * DIN_);
        float4* dst = (float4*)so8;
#pragma unroll
        for (int i = 0; i < 8; i++)
            dst[i * 512 + tid] = src[i * 512 + tid];
    }
    __syncthreads();

    // ---- GEMM slice: warp w computes d = r*16 + w for all 8 rows ----
    {
        int dg = r * 16 + w;
        const float4* w4 = (const float4*)W + (size_t)dg * (DIN_ / 4);
        const float4* so4 = (const float4*)so8;
        float acc[8];
#pragma unroll
        for (int j = 0; j < 8; j++) acc[j] = 0.0f;

#pragma unroll 4
        for (int it = 0; it < 16; it++) {
            float4 wv = w4[it * 32 + lane];
#pragma unroll
            for (int j = 0; j < 8; j++) {
                float4 ov = so4[j * 512 + it * 32 + lane];
                float a = acc[j];
                a = fmaf(wv.x, ov.x, a);
                a = fmaf(wv.y, ov.y, a);
                a = fmaf(wv.z, ov.z, a);
                a = fmaf(wv.w, ov.w, a);
                acc[j] = a;
            }
        }
        // butterfly each row-sum; lane j keeps row j's value
        float mine = 0.0f;
#pragma unroll
        for (int j = 0; j < 8; j++) {
            float t = acc[j];
#pragma unroll
            for (int o = 16; o; o >>= 1) t += __shfl_xor_sync(FULL, t, o);
            if (lane == j) mine = t;
        }
        // lane j sends (value + bias[dg]) to cluster CTA j's semb[dg]
        if (lane < 8) {
            float val = mine + bias[dg];
            unsigned addr = (unsigned)__cvta_generic_to_shared(&semb[dg]);
            st_shared_cluster_f32_(mapa_shared_(addr, (unsigned)lane), val);
        }
    }
    cluster_sync_();   // all DSMEM scatters visible; block barrier included

    // ---- normalize own row's emb ----
    float4 e = ((const float4*)semb)[lane];
    float ssq = e.x * e.x + e.y * e.y + e.z * e.z + e.w * e.w;
#pragma unroll
    for (int o = 16; o; o >>= 1) ssq += __shfl_xor_sync(FULL, ssq, o);
    float inv = 1.0f / fmaxf(sqrtf(ssq), 1e-12f);
    e.x *= inv; e.y *= inv; e.z *= inv; e.w *= inv;

    const float4* mb4 = (const float4*)mbank;
    const int* ri = ridx + (size_t)b * M_;

    // ---- gather + dot: 256 negs per warp (R9 body) ----
    int m0 = w * 256;
    for (int mb_ = m0; mb_ < m0 + 256; mb_ += 32) {
        int myIdx = ri[mb_ + lane];
#pragma unroll 8
        for (int j = 0; j < 32; j++) {
            int idx = __shfl_sync(FULL, myIdx, j);
            float4 v = mb4[(size_t)idx * 32 + lane];
            float d = v.x * e.x + v.y * e.y;
            d = fmaf(v.z, e.z, d);
            d = fmaf(v.w, e.w, d);
#pragma unroll
            for (int o = 16; o; o >>= 1) d += __shfl_xor_sync(FULL, d, o);
            if (lane == j) sneg[mb_ + j] = d * TAU_INV;
        }
    }
    __syncthreads();

    // ---- each thread owns 8 negs (stride 512, conflict-free) ----
    float vl[8];
    float mx = -3.0e38f;
#pragma unroll
    for (int i = 0; i < 8; i++) {
        vl[i] = sneg[tid + i * 512];
        mx = fmaxf(mx, vl[i]);
    }
#pragma unroll
    for (int o = 16; o; o >>= 1) mx = fmaxf(mx, __shfl_xor_sync(FULL, mx, o));
    if (lane == 0) sr[w] = mx;
    __syncthreads();
    if (w == 0) {
        float t2 = sr[lane & 15];
#pragma unroll
        for (int o = 8; o; o >>= 1) t2 = fmaxf(t2, __shfl_xor_sync(FULL, t2, o));
        if (lane == 0) sr[32] = t2;
    }
    __syncthreads();
    float Mx = sr[32];

    float se = 0.f;
#pragma unroll
    for (int i = 0; i < 8; i++) se += __expf(vl[i] - Mx);
#pragma unroll
    for (int o = 16; o; o >>= 1) se += __shfl_xor_sync(FULL, se, o);
    __syncthreads();
    if (lane == 0) sr[w] = se;
    __syncthreads();
    if (w == 0) {
        float t2 = (lane < 16) ? sr[lane] : 0.f;
#pragma unroll
        for (int o = 8; o; o >>= 1) t2 += __shfl_xor_sync(FULL, t2, o);
        if (lane == 0) sr[32] = Mx + __logf(t2);
    }
    __syncthreads();
    float logC = sr[32];

    // noise loss: sum softplus(neg - logC)
    float ns = 0.f;
#pragma unroll
    for (int i = 0; i < 8; i++) {
        float x = vl[i] - logC;
        ns += (x > 15.f) ? x : log1pf(__expf(x));
    }
#pragma unroll
    for (int o = 16; o; o >>= 1) ns += __shfl_xor_sync(FULL, ns, o);
    __syncthreads();
    if (lane == 0) sr[w] = ns;
    __syncthreads();
    if (w == 0) {
        float t2 = (lane < 16) ? sr[lane] : 0.f;
#pragma unroll
        for (int o = 8; o; o >>= 1) t2 += __shfl_xor_sync(FULL, t2, o);
        if (lane == 0) g_nl[b] = t2;
    }

    // ---- warp 0: positive term + entries + per-row data loss ----
    if (w == 0) {
        int pidx = indices[b];
        float4 p = mb4[(size_t)pidx * 32 + lane];
        float d = p.x * e.x + p.y * e.y;
        d = fmaf(p.z, e.z, d);
        d = fmaf(p.w, e.w, d);
#pragma unroll
        for (int o = 16; o; o >>= 1) d += __shfl_xor_sync(FULL, d, o);
        float pos = d * TAU_INV;

        float4 ent;
        ent.x = 0.5f * (p.x + e.x);
        ent.y = 0.5f * (p.y + e.y);
        ent.z = 0.5f * (p.z + e.z);
        ent.w = 0.5f * (p.w + e.w);
        float nsq = ent.x * ent.x + ent.y * ent.y + ent.z * ent.z + ent.w * ent.w;
#pragma unroll
        for (int o = 16; o; o >>= 1) nsq += __shfl_xor_sync(FULL, nsq, o);
        float inv2 = 1.0f / fmaxf(sqrtf(nsq), 1e-12f);
        ent.x *= inv2; ent.y *= inv2; ent.z *= inv2; ent.w *= inv2;

        int base = 1 + b * D_ + lane * 4;
        out[base + 0] = ent.x;
        out[base + 1] = ent.y;
        out[base + 2] = ent.z;
        out[base + 3] = ent.w;

        if (lane == 0) {
            float x = logC - pos;
            g_dl[b] = (x > 15.f) ? x : log1pf(__expf(x));
        }
    }
}

// ---------------- finalize scalars (reduce 256 per-row losses) ---------------
__global__ void __launch_bounds__(256) kFinal(float* __restrict__ out) {
    __shared__ float s[16];
    int tid = threadIdx.x, w = tid >> 5, lane = tid & 31;
    float dl = g_dl[tid];
    float nl = g_nl[tid];
#pragma unroll
    for (int o = 16; o; o >>= 1) {
        dl += __shfl_xor_sync(FULL, dl, o);
        nl += __shfl_xor_sync(FULL, nl, o);
    }
    if (lane == 0) { s[w] = dl; s[w + 8] = nl; }
    __syncthreads();
    if (tid == 0) {
        float dsum = 0.f, nsum = 0.f;
#pragma unroll
        for (int i = 0; i < 8; i++) { dsum += s[i]; nsum += s[i + 8]; }
        dsum *= (1.0f / (float)B_);
        nsum *= (1.0f / (float)B_);
        out[0] = dsum + nsum;
        out[1 + B_ * D_]     = dsum;
        out[1 + B_ * D_ + 1] = nsum;
    }
}

// ---------------- launcher ----------------------------------------------------
extern "C" void kernel_launch(void* const* d_in, const int* in_sizes, int n_in,
                              void* d_out, int out_size) {
    const float* outputs = (const float*)d_in[0];
    const float* W       = (const float*)d_in[1];
    const float* bias    = (const float*)d_in[2];
    const float* mbank   = (const float*)d_in[3];
    const int*   indices = (const int*)d_in[4];
    const int*   ridx    = (const int*)d_in[5];
    float* out = (float*)d_out;

    static int smem_set = 0;
    if (!smem_set) {
        cudaFuncSetAttribute(kMain, cudaFuncAttributeMaxDynamicSharedMemorySize,
                             SMEM_BYTES);
        smem_set = 1;
    }

    kMain<<<256, 512, SMEM_BYTES>>>(outputs, W, bias, mbank, indices, ridx, out);
    kFinal<<<1, 256>>>(out);
}